// round 5
// baseline (speedup 1.0000x reference)
#include <cuda_runtime.h>
#include <cstdint>

// ---------------------------------------------------------------------------
// Block-diagonal linear (256x0e+256x1o+256x2e) as 3 GEMMs over rows (z,i):
//   A'[z*d+i][u] = feat[z, xoff + u*d + i];  C = A' * W_b / 16.
// Persistent weight-resident design: CTA owns (block d, N-half of 128 cols),
// keeps B (128x256 tf32, fragment-order) in smem for its whole life, loops
// over M-tiles of 256 rows. A staged coalesced (LDG.128 over the contiguous
// per-z span) -> swizzled scatter STS into fragment-order smem.
// mma.sync m16n8k8 tf32 (PTX targets compute_103; tcgen05 unavailable).
// ---------------------------------------------------------------------------
#define HX_BZ   50000
#define HX_FEAT 2304

static constexpr int GRID     = 148;
static constexpr int NTHREADS = 512;   // 16 warps: wm = wid&3 (M64), wn = wid>>2 (N32)
static constexpr int TMROWS   = 256;   // rows per tile
static constexpr int KC       = 32;    // k per chunk
static constexpr int NCH      = 8;     // 256 / 32

// smem bytes: B resident 8192 uint4 = 128KB; A double buffer 2 x 32KB
static constexpr int SM_B     = 0;
static constexpr int SM_A0    = 131072;
static constexpr int SM_A1    = 163840;
static constexpr int SM_BYTES = 196608;

// ---------------------------------------------------------------------------
__device__ __forceinline__ uint32_t f2tf(float x) {
    uint32_t r;
    asm("cvt.rna.tf32.f32 %0, %1;" : "=r"(r) : "f"(x));
    return r;
}

__device__ __forceinline__ void mma8(float* c, const uint32_t* a,
                                     uint32_t b0, uint32_t b1) {
    asm volatile(
        "mma.sync.aligned.m16n8k8.row.col.f32.tf32.tf32.f32 "
        "{%0,%1,%2,%3}, {%4,%5,%6,%7}, {%8,%9}, {%0,%1,%2,%3};"
        : "+f"(c[0]), "+f"(c[1]), "+f"(c[2]), "+f"(c[3])
        : "r"(a[0]), "r"(a[1]), "r"(a[2]), "r"(a[3]), "r"(b0), "r"(b1));
}

// ---------------------------------------------------------------------------
template<int D, int XOFF, int WOFF, int TILES, int MTOT>
__global__ void __launch_bounds__(NTHREADS, 1)
lin_kernel(const float* __restrict__ feat,
           const float* __restrict__ wt,
           float* __restrict__ out)
{
    extern __shared__ char smem[];
    const int tid  = threadIdx.x;
    const int lane = tid & 31;
    const int wid  = tid >> 5;
    const int g    = lane >> 2;
    const int tg   = lane & 3;
    const int wm   = wid & 3;     // M: rows wm*64 .. +63
    const int wn   = wid >> 2;    // N: cols wn*32 .. +31 (within the 128 half)

    constexpr int F4PZ = 8 * D;                 // float4 per z per chunk
    constexpr int PMAX = (D == 1) ? 4 : 5;      // staged float4 per thread

    // fixed per-thread staging decode (e -> (z_idx, q))
    int zidx[PMAX], q4[PMAX];
    #pragma unroll
    for (int p = 0; p < PMAX; p++) {
        const int e = tid + NTHREADS * p;
        zidx[p] = e / F4PZ;
        q4[p]   = (e % F4PZ) * 4;
    }

    float4 rA[PMAX];

    // ---- stage B once (fragment order, vec4 = (k,n),(k+4,n),(k,n+8),(k+4,n+8)) ----
    auto stageB = [&](int h) {
        uint4* B4 = (uint4*)(smem + SM_B);
        #pragma unroll
        for (int p = 0; p < 16; p++) {
            const int e   = tid + NTHREADS * p;
            const int tt  = e & 3, gg = (e >> 2) & 7;
            const int idx = e >> 5;
            const int nfp = idx & 1, wnn = (idx >> 1) & 3, ss = idx >> 3;
            const int k   = ss * 8 + tt;
            const int n   = h * 128 + wnn * 32 + nfp * 16 + gg;
            const float* wp = wt + WOFF + k * 256 + n;
            uint4 v;
            v.x = f2tf(wp[0]);    v.y = f2tf(wp[1024]);
            v.z = f2tf(wp[8]);    v.w = f2tf(wp[1032]);
            B4[e] = v;
        }
    };

    // ---- coalesced A chunk load (contiguous span per z) ----
    auto ldgA = [&](int zl, int ch) {
        #pragma unroll
        for (int p = 0; p < PMAX; p++) {
            const int zt = zl + zidx[p];
            if (zt < HX_BZ) {
                const float* src =
                    feat + (size_t)zt * HX_FEAT + XOFF + ch * (KC * D) + q4[p];
                rA[p] = *(const float4*)src;
            } else {
                rA[p] = make_float4(0.f, 0.f, 0.f, 0.f);
            }
        }
    };

    // ---- scatter STS into fragment-order A buffer, XOR swizzle slot^(5s) ----
    auto stsA = [&](int parity, int ro) {
        char* Ab = smem + (parity ? SM_A1 : SM_A0);
        #pragma unroll
        for (int p = 0; p < PMAX; p++) {
            const int rbase = zidx[p] * D + ro;
            const float v[4] = {rA[p].x, rA[p].y, rA[p].z, rA[p].w};
            #pragma unroll
            for (int jj = 0; jj < 4; jj++) {
                const int pos = q4[p] + jj;
                const int kl  = pos / D;            // compile-time D
                const int ii  = pos - kl * D;
                const int row = rbase + ii;
                if ((unsigned)row < 256u) {
                    const int slot = (((row & 7) << 2) | (kl & 3)) ^ ((kl >> 3) * 5);
                    const uint32_t off =
                        (uint32_t)(((kl >> 3) * 16 + (row >> 4)) * 512
                                   + slot * 16
                                   + ((row >> 3) & 1) * 4
                                   + ((kl >> 2) & 1) * 8);
                    *(uint32_t*)(Ab + off) = f2tf(v[jj]);
                }
            }
        }
    };

    float c[4][4][4];

    auto compute = [&](int ch) {
        const uint4* A4 = (const uint4*)(smem + ((ch & 1) ? SM_A1 : SM_A0));
        const uint4* B4 = (const uint4*)(smem + SM_B);
        #pragma unroll
        for (int s = 0; s < 4; s++) {
            const int sl = lane ^ (s * 5);
            uint4 av[4];
            #pragma unroll
            for (int mf = 0; mf < 4; mf++)
                av[mf] = A4[(s * 16 + wm * 4 + mf) * 32 + sl];
            #pragma unroll
            for (int nfp = 0; nfp < 2; nfp++) {
                const uint4 bv = B4[(((ch * 4 + s) * 4 + wn) * 2 + nfp) * 32 + lane];
                #pragma unroll
                for (int mf = 0; mf < 4; mf++) {
                    mma8(c[mf][nfp * 2 + 0], (const uint32_t*)&av[mf], bv.x, bv.y);
                    mma8(c[mf][nfp * 2 + 1], (const uint32_t*)&av[mf], bv.z, bv.w);
                }
            }
        }
    };

    // ---- persistent job loop: j in [0, 2*TILES), half-major ordering ----
    int j = blockIdx.x;
    if (j >= 2 * TILES) return;
    int half = (j >= TILES) ? 1 : 0;
    int m0   = (j - half * TILES) * TMROWS;
    int zlo  = m0 / D;
    int roff = zlo * D - m0;
    int curh = -1;

    ldgA(zlo, 0);

    while (true) {
        if (half != curh) {          // uniform per CTA
            __syncthreads();         // drain any compute on old B
            stageB(half);
            curh = half;
        }

        #pragma unroll
        for (int mf = 0; mf < 4; mf++)
            #pragma unroll
            for (int nf = 0; nf < 4; nf++)
                #pragma unroll
                for (int q = 0; q < 4; q++) c[mf][nf][q] = 0.0f;

        stsA(0, roff);
        __syncthreads();
        ldgA(zlo, 1);

        #pragma unroll 1
        for (int ch = 0; ch < NCH - 1; ch++) {
            compute(ch);
            stsA((ch + 1) & 1, roff);
            __syncthreads();
            if (ch < NCH - 2) ldgA(zlo, ch + 2);
        }

        // prefetch next tile's chunk 0 before the last compute + epilogue
        const int jn = j + GRID;
        const bool more = (jn < 2 * TILES);
        int nh = half, nm0 = m0, nzlo = zlo, nroff = roff;
        if (more) {
            nh    = (jn >= TILES) ? 1 : 0;
            nm0   = (jn - nh * TILES) * TMROWS;
            nzlo  = nm0 / D;
            nroff = nzlo * D - nm0;
            ldgA(nzlo, 0);
        }

        compute(NCH - 1);

        // ---- epilogue: scatter rows (z,i), scale 1/sqrt(256) ----
        const float S = 0.0625f;
        #pragma unroll
        for (int mf = 0; mf < 4; mf++) {
            #pragma unroll
            for (int rr = 0; rr < 2; rr++) {
                const int row = wm * 64 + mf * 16 + rr * 8 + g;
                const int rg  = m0 + row;
                if (rg < MTOT) {
                    const int z  = rg / D;
                    const int ii = rg - z * D;
                    float* op = out + (size_t)z * HX_FEAT + XOFF + ii;
                    #pragma unroll
                    for (int nf = 0; nf < 4; nf++) {
                        const int n = half * 128 + wn * 32 + (nf >> 1) * 16
                                    + (nf & 1) * 8 + 2 * tg;
                        if (D == 1) {
                            float2 v2;
                            v2.x = c[mf][nf][rr * 2 + 0] * S;
                            v2.y = c[mf][nf][rr * 2 + 1] * S;
                            *(float2*)(op + n) = v2;
                        } else {
                            op[(size_t)n * D]       = c[mf][nf][rr * 2 + 0] * S;
                            op[(size_t)(n + 1) * D] = c[mf][nf][rr * 2 + 1] * S;
                        }
                    }
                }
            }
        }

        if (!more) break;
        j = jn; half = nh; m0 = nm0; zlo = nzlo; roff = nroff;
    }
}

// ---------------------------------------------------------------------------
extern "C" void kernel_launch(void* const* d_in, const int* in_sizes, int n_in,
                              void* d_out, int out_size) {
    const float* feat = (const float*)d_in[0];
    const float* wt   = (const float*)d_in[1];
    float* out        = (float*)d_out;

    // tiles: ceil(50000/256)=196, ceil(150000/256)=586, ceil(250000/256)=977
    auto k1 = lin_kernel<1, 0,    0,      196, 50000>;
    auto k3 = lin_kernel<3, 256,  65536,  586, 150000>;
    auto k5 = lin_kernel<5, 1024, 131072, 977, 250000>;

    cudaFuncSetAttribute(k1, cudaFuncAttributeMaxDynamicSharedMemorySize, SM_BYTES);
    cudaFuncSetAttribute(k3, cudaFuncAttributeMaxDynamicSharedMemorySize, SM_BYTES);
    cudaFuncSetAttribute(k5, cudaFuncAttributeMaxDynamicSharedMemorySize, SM_BYTES);

    k1<<<GRID, NTHREADS, SM_BYTES>>>(feat, wt, out);
    k3<<<GRID, NTHREADS, SM_BYTES>>>(feat, wt, out);
    k5<<<GRID, NTHREADS, SM_BYTES>>>(feat, wt, out);
}

// round 6
// speedup vs baseline: 1.2289x; 1.2289x over previous
#include <cuda_runtime.h>
#include <cstdint>

// ---------------------------------------------------------------------------
// Block-diagonal linear (256x0e+256x1o+256x2e): 3 GEMMs over rows (z,i):
//   A'[z*D+i][u] = feat[z, XOFF + u*D + i];  C = A' * W_b / 16.
// Persistent kernel, B-resident (N-half, 128KB). 512 threads = TWO independent
// 256-thread halves (own 128-row subtile, own A buffers, named barriers),
// sharing B -> barrier/tensor overlap at 1 CTA/SM.
// A staged row-major stride-36 (conflict-free frag LDS + STS for all D).
// D>1 epilogue: smem transpose (stride 72, STS.64 conflict-free) -> coalesced
// STG.128 of contiguous per-z spans. mma.sync m16n8k8 tf32.
// ---------------------------------------------------------------------------
#define HX_BZ   50000
#define HX_FEAT 2304

static constexpr int NTH     = 512;
static constexpr int SM_B    = 0;        // 8192 uint4 = 131072 B
static constexpr int SM_A    = 131072;   // two halves x 36864
static constexpr int A_HALF  = 36864;
static constexpr int A_BUF   = 18432;    // 128 rows x 36 words x 4B
static constexpr int SM_BYTES = 131072 + 2 * A_HALF;   // 204800

// job segments: (d-block, n-half); tiles of 256 rows
//   d1:196  d3:586  d5:977  (x2 n-halves)
static constexpr int P1 = 196, P2 = 782, P3 = 1759, P4 = 1955, P5 = 2541, P6 = 3518;

// ---------------------------------------------------------------------------
__device__ __forceinline__ uint32_t f2tf(float x) {
    uint32_t r;
    asm("cvt.rna.tf32.f32 %0, %1;" : "=r"(r) : "f"(x));
    return r;
}

__device__ __forceinline__ void mma8(float* c, const uint32_t* a,
                                     uint32_t b0, uint32_t b1) {
    asm volatile(
        "mma.sync.aligned.m16n8k8.row.col.f32.tf32.tf32.f32 "
        "{%0,%1,%2,%3}, {%4,%5,%6,%7}, {%8,%9}, {%0,%1,%2,%3};"
        : "+f"(c[0]), "+f"(c[1]), "+f"(c[2]), "+f"(c[3])
        : "r"(a[0]), "r"(a[1]), "r"(a[2]), "r"(a[3]), "r"(b0), "r"(b1));
}

__device__ __forceinline__ void barh(int h) {
    asm volatile("bar.sync %0, %1;" :: "r"(h + 1), "r"(256) : "memory");
}

// ---------------------------------------------------------------------------
// Stage resident B (fragment order): uint4 e -> ((ch4s)*4+wn)*2+nfp)*32+lane
// vec4 = W[k,n], W[k+4,n], W[k,n+8], W[k+4,n+8]  (tf32)
__device__ __forceinline__ void stageB(char* smem, const float* __restrict__ wt,
                                       int woff, int nh, int tid) {
    uint4* B4 = (uint4*)(smem + SM_B);
    #pragma unroll
    for (int p = 0; p < 16; p++) {
        const int e   = tid + NTH * p;
        const int tt  = e & 3, gg = (e >> 2) & 7;
        const int idx = e >> 5;
        const int nfp = idx & 1, wnn = (idx >> 1) & 3, ss = idx >> 3;
        const int k   = ss * 8 + tt;
        const int n   = nh * 128 + wnn * 32 + nfp * 16 + gg;
        const float* wp = wt + woff + k * 256 + n;
        uint4 v;
        v.x = f2tf(wp[0]);    v.y = f2tf(wp[1024]);
        v.z = f2tf(wp[8]);    v.w = f2tf(wp[1032]);
        B4[e] = v;
    }
}

// ---------------------------------------------------------------------------
template<int D, int XOFF>
__device__ __forceinline__ void process_tile(
    const float* __restrict__ feat, float* __restrict__ out,
    char* smem, int tile, int nh,
    int tid2, int h, int lane, int g, int tg, int wm, int wn)
{
    const int m0h = tile * 256 + h * 128;
    const int z0  = m0h / D;
    const int z1  = (m0h + 127) / D;
    const int nzc = z1 - z0 + 1;
    const int totalf4 = nzc * 8 * D;
    constexpr int PM = (D == 1) ? 4 : 5;

    char* As0 = smem + SM_A + h * A_HALF;
    char* As1 = As0 + A_BUF;

    // per-thread staging decode
    int vzl[PM], vq4[PM]; bool vok[PM];
    #pragma unroll
    for (int p = 0; p < PM; p++) {
        const int v = tid2 + 256 * p;
        vok[p] = (v < totalf4);
        vzl[p] = v / (8 * D);
        vq4[p] = (v - vzl[p] * (8 * D)) * 4;
    }

    float4 rA[PM];

    auto ldgA = [&](int ch) {
        #pragma unroll
        for (int p = 0; p < PM; p++) {
            const int z = z0 + vzl[p];
            if (vok[p] && z < HX_BZ)
                rA[p] = *(const float4*)(feat + (size_t)z * HX_FEAT + XOFF
                                         + ch * (32 * D) + vq4[p]);
            else
                rA[p] = make_float4(0.f, 0.f, 0.f, 0.f);
        }
    };

    auto stsA = [&](char* Ab) {
        #pragma unroll
        for (int p = 0; p < PM; p++) {
            if (!vok[p]) continue;
            const int row0 = (z0 + vzl[p]) * D - m0h;
            const float vv[4] = {rA[p].x, rA[p].y, rA[p].z, rA[p].w};
            if (D == 1) {
                uint4 q;
                q.x = f2tf(vv[0]); q.y = f2tf(vv[1]);
                q.z = f2tf(vv[2]); q.w = f2tf(vv[3]);
                *(uint4*)(Ab + (uint32_t)(row0 * 36 + vq4[p]) * 4) = q;
            } else {
                #pragma unroll
                for (int jj = 0; jj < 4; jj++) {
                    const int pos = vq4[p] + jj;
                    const int kl  = pos / D;
                    const int ii  = pos - kl * D;
                    const int row = row0 + ii;
                    if ((unsigned)row < 128u)
                        *(uint32_t*)(Ab + (uint32_t)(row * 36 + kl) * 4) = f2tf(vv[jj]);
                }
            }
        }
    };

    float c[4][4][4];
    #pragma unroll
    for (int mf = 0; mf < 4; mf++)
        #pragma unroll
        for (int nf = 0; nf < 4; nf++)
            #pragma unroll
            for (int q = 0; q < 4; q++) c[mf][nf][q] = 0.f;

    auto compute = [&](int ch, const char* Ab) {
        const uint32_t* A32 = (const uint32_t*)Ab;
        const uint4* B4 = (const uint4*)(smem + SM_B);
        #pragma unroll
        for (int s = 0; s < 4; s++) {
            uint32_t a[4][4];
            #pragma unroll
            for (int mf = 0; mf < 4; mf++) {
                const int row = wm * 64 + mf * 16 + g;
                const int k   = s * 8 + tg;
                a[mf][0] = A32[row * 36 + k];
                a[mf][1] = A32[(row + 8) * 36 + k];
                a[mf][2] = A32[row * 36 + k + 4];
                a[mf][3] = A32[(row + 8) * 36 + k + 4];
            }
            #pragma unroll
            for (int nfp = 0; nfp < 2; nfp++) {
                const uint4 bv = B4[((((ch * 4 + s) * 4 + wn) * 2 + nfp)) * 32 + lane];
                #pragma unroll
                for (int mf = 0; mf < 4; mf++) {
                    mma8(c[mf][nfp * 2 + 0], a[mf], bv.x, bv.y);
                    mma8(c[mf][nfp * 2 + 1], a[mf], bv.z, bv.w);
                }
            }
        }
    };

    // ---- k pipeline ----
    ldgA(0);
    stsA(As0); barh(h); ldgA(1);
    #pragma unroll 1
    for (int ch = 0; ch < 8; ch++) {
        compute(ch, (ch & 1) ? As1 : As0);
        if (ch < 7) {
            stsA((ch & 1) ? As0 : As1);
            barh(h);
            if (ch < 6) ldgA(ch + 2);
        }
    }

    // ---- epilogue ----
    const float S = 0.0625f;
    if (D == 1) {
        #pragma unroll
        for (int mf = 0; mf < 4; mf++)
            #pragma unroll
            for (int rr = 0; rr < 2; rr++) {
                const int row = wm * 64 + mf * 16 + rr * 8 + g;
                const int z   = m0h + row;
                if (z < HX_BZ) {
                    float* op = out + (size_t)z * HX_FEAT + XOFF + nh * 128;
                    #pragma unroll
                    for (int nf = 0; nf < 4; nf++) {
                        const int n = wn * 32 + (nf >> 1) * 16 + (nf & 1) * 8 + 2 * tg;
                        float2 v;
                        v.x = c[mf][nf][rr * 2 + 0] * S;
                        v.y = c[mf][nf][rr * 2 + 1] * S;
                        *(float2*)(op + n) = v;
                    }
                }
            }
    } else {
        barh(h);                         // all compute done before scratch reuse
        float* scr = (float*)As0;        // 128 rows x 72 words = 36864 B
        #pragma unroll 1
        for (int q = 0; q < 2; q++) {
            if ((wn >> 1) == q) {        // writer warps for this n-quarter
                #pragma unroll
                for (int mf = 0; mf < 4; mf++)
                    #pragma unroll
                    for (int nf = 0; nf < 4; nf++)
                        #pragma unroll
                        for (int rr = 0; rr < 2; rr++) {
                            const int row = wm * 64 + mf * 16 + rr * 8 + g;
                            const int nl  = (wn & 1) * 32 + (nf >> 1) * 16
                                          + (nf & 1) * 8 + 2 * tg;
                            float2 v;
                            v.x = c[mf][nf][rr * 2 + 0] * S;
                            v.y = c[mf][nf][rr * 2 + 1] * S;
                            *(float2*)(scr + row * 72 + nl) = v;
                        }
            }
            barh(h);
            // readers: contiguous per-z spans of 64*D floats
            const int base = (nh * 128 + q * 64) * D;
            const int t16  = 16 * D;
            const int tot4 = nzc * t16;
            #pragma unroll 1
            for (int p = 0; p < 9; p++) {
                const int v = tid2 + 256 * p;
                if (v < tot4) {
                    const int vz = v / t16;
                    const int t0 = (v - vz * t16) * 4;
                    const int z  = z0 + vz;
                    if (z < HX_BZ) {
                        const int row0 = z * D - m0h;
                        float f[4]; bool ok[4]; bool all = true;
                        #pragma unroll
                        for (int e = 0; e < 4; e++) {
                            const int t = t0 + e;
                            const int n = t / D;
                            const int i = t - n * D;
                            const int row = row0 + i;
                            ok[e] = ((unsigned)row < 128u);
                            all &= ok[e];
                            f[e] = ok[e] ? scr[row * 72 + n] : 0.f;
                        }
                        float* op = out + (size_t)z * HX_FEAT + XOFF + base + t0;
                        if (all) {
                            *(float4*)op = make_float4(f[0], f[1], f[2], f[3]);
                        } else {
                            #pragma unroll
                            for (int e = 0; e < 4; e++) if (ok[e]) op[e] = f[e];
                        }
                    }
                }
            }
            barh(h);   // readers done before next writer pass / next tile stsA
        }
    }
}

// ---------------------------------------------------------------------------
__global__ void __launch_bounds__(NTH, 1)
lin_all(const float* __restrict__ feat, const float* __restrict__ wt,
        float* __restrict__ out)
{
    extern __shared__ char smem[];
    const int tid  = threadIdx.x;
    const int lane = tid & 31;
    const int wid  = tid >> 5;
    const int h    = wid >> 3;        // half id
    const int w    = wid & 7;         // warp within half
    const int tid2 = tid & 255;       // thread within half
    const int g    = lane >> 2;
    const int tg   = lane & 3;
    const int wm   = w >> 2;          // 2 M positions of 64 rows
    const int wn   = w & 3;           // 4 N positions of 32 cols

    const int G = gridDim.x;
    int j = blockIdx.x;
    int curseg = -1;

    while (j < P6) {
        int seg, tile;
        if      (j < P1) { seg = 0; tile = j;      }
        else if (j < P2) { seg = 1; tile = j - P1; }
        else if (j < P3) { seg = 2; tile = j - P2; }
        else if (j < P4) { seg = 3; tile = j - P3; }
        else if (j < P5) { seg = 4; tile = j - P4; }
        else             { seg = 5; tile = j - P5; }
        const int b  = (seg < 3) ? seg : seg - 3;
        const int nh = (seg >= 3) ? 1 : 0;

        if (seg != curseg) {
            __syncthreads();
            const int woff = (b == 0) ? 0 : (b == 1) ? 65536 : 131072;
            stageB(smem, wt, woff, nh, tid);
            __syncthreads();
            curseg = seg;
        }

        if (b == 0)
            process_tile<1, 0>(feat, out, smem, tile, nh, tid2, h, lane, g, tg, wm, wn);
        else if (b == 1)
            process_tile<3, 256>(feat, out, smem, tile, nh, tid2, h, lane, g, tg, wm, wn);
        else
            process_tile<5, 1024>(feat, out, smem, tile, nh, tid2, h, lane, g, tg, wm, wn);

        j += G;
    }
}

// ---------------------------------------------------------------------------
extern "C" void kernel_launch(void* const* d_in, const int* in_sizes, int n_in,
                              void* d_out, int out_size) {
    const float* feat = (const float*)d_in[0];
    const float* wt   = (const float*)d_in[1];
    float* out        = (float*)d_out;

    int sms = 148;
    cudaDeviceGetAttribute(&sms, cudaDevAttrMultiProcessorCount, 0);

    cudaFuncSetAttribute(lin_all,
                         cudaFuncAttributeMaxDynamicSharedMemorySize, SM_BYTES);

    lin_all<<<sms, NTH, SM_BYTES>>>(feat, wt, out);
}

// round 7
// speedup vs baseline: 3.5064x; 2.8534x over previous
#include <cuda_runtime.h>
#include <cstdint>

// ---------------------------------------------------------------------------
// Block-diagonal linear (256x0e+256x1o+256x2e): 3 GEMMs over rows (z,i):
//   A'[z*D+i][u] = feat[z, XOFF + u*D + i];  C = A' * W_b / 16.
// This round: 256-thread CTAs, 2 CTAs/SM (co-CTA hides barriers/latency),
// tile 128x128, warp tile 32x64, 3-stage cp.async ring with ONE barrier per
// k-chunk. A kept in NATIVE per-z layout in smem (pure cp.async.16 staging,
// all D); fragment loads do the (k,i) decode with conflict-aware padding.
// mma.sync m16n8k8 tf32 (PTX targets compute_103; tcgen05 unavailable).
// ---------------------------------------------------------------------------
#define HX_BZ   50000
#define HX_FEAT 2304

static constexpr int NTH = 256;        // 8 warps: wm = wid>>1 (4x32 rows), wn = wid&1 (2x64 cols)
static constexpr int SB  = 136;        // B row stride (floats): (8tg+g) banks, conflict-free

// ---------------------------------------------------------------------------
__device__ __forceinline__ uint32_t f2tf(float x) {
    uint32_t r;
    asm("cvt.rna.tf32.f32 %0, %1;" : "=r"(r) : "f"(x));
    return r;
}

__device__ __forceinline__ void mma8(float* c, const uint32_t* a,
                                     uint32_t b0, uint32_t b1) {
    asm volatile(
        "mma.sync.aligned.m16n8k8.row.col.f32.tf32.tf32.f32 "
        "{%0,%1,%2,%3}, {%4,%5,%6,%7}, {%8,%9}, {%0,%1,%2,%3};"
        : "+f"(c[0]), "+f"(c[1]), "+f"(c[2]), "+f"(c[3])
        : "r"(a[0]), "r"(a[1]), "r"(a[2]), "r"(a[3]), "r"(b0), "r"(b1));
}

#define CP_A16(dst, src, sz)                                               \
    asm volatile("cp.async.cg.shared.global [%0], [%1], 16, %2;"           \
                 :: "r"(dst), "l"(src), "r"(sz) : "memory")
#define CP_COMMIT() asm volatile("cp.async.commit_group;" ::: "memory")
#define CP_WAIT(n)  asm volatile("cp.async.wait_group %0;" :: "n"(n) : "memory")

__device__ __forceinline__ uint32_t smem_u32(const void* p) {
    uint32_t a;
    asm("{ .reg .u64 t; cvta.to.shared.u64 t, %1; cvt.u32.u64 %0, t; }"
        : "=r"(a) : "l"(p));
    return a;
}

// ---------------------------------------------------------------------------
template<int D, int XOFF, int WOFF, int MTOT>
__global__ void __launch_bounds__(NTH, 2)
lin_k(const float* __restrict__ feat, const float* __restrict__ wt,
      float* __restrict__ out)
{
    // A row stride (floats): pad so frag banks = 8*zrel + D*tg + i  (<=2-way)
    constexpr int SD  = (D == 1) ? 36 : (D == 3) ? 104 : 168;
    constexpr int NZ  = (D == 1) ? 128 : (D == 3) ? 44 : 27;   // z rows staged
    constexpr int F4Z = 8 * D;                // float4 per z per chunk
    constexpr int TOT4 = NZ * F4Z;            // 1024 / 1056 / 1080
    constexpr int PA  = (TOT4 + NTH - 1) / NTH;
    constexpr int ABUF = NZ * SD * 4;         // bytes
    constexpr int BBUF = 32 * SB * 4;
    constexpr int STG  = ABUF + BBUF;

    extern __shared__ char smem[];
    const uint32_t smb = smem_u32(smem);

    const int tid  = threadIdx.x;
    const int lane = tid & 31;
    const int wid  = tid >> 5;
    const int g    = lane >> 2;
    const int tg   = lane & 3;
    const int wm   = wid >> 1;      // 4 x 32 rows
    const int wn   = wid & 1;       // 2 x 64 cols

    const int bid  = blockIdx.x;
    const int tile = bid >> 1;
    const int nh   = bid & 1;
    const int m0   = tile * 128;
    const int z0   = m0 / D;

    // ---- A staging decode: PA float4 per thread ----
    const char* asrc[PA];
    uint32_t    adst[PA];
    uint32_t    aszr[PA];
    #pragma unroll
    for (int p = 0; p < PA; p++) {
        const int e = tid + NTH * p;
        const int zr = e / F4Z;
        const int q  = e - zr * F4Z;
        const int z  = z0 + zr;
        const bool ok = (e < TOT4) && (z < HX_BZ);
        aszr[p] = ok ? 16u : 0u;
        asrc[p] = (const char*)(feat + (size_t)z * HX_FEAT + XOFF) + q * 16;
        adst[p] = (uint32_t)(zr * SD * 4 + q * 16);
        if (e >= TOT4) adst[p] = 0xFFFFFFFFu;   // skip flag
    }

    // ---- B staging decode: 4 float4 per thread ----
    const char* bsrc[4];
    uint32_t    bdst[4];
    #pragma unroll
    for (int p = 0; p < 4; p++) {
        const int e  = tid + NTH * p;
        const int k  = e >> 5;
        const int n4 = e & 31;
        bsrc[p] = (const char*)(wt + WOFF + (size_t)k * 256 + nh * 128 + n4 * 4);
        bdst[p] = (uint32_t)(ABUF + (k * SB + n4 * 4) * 4);
    }

    auto issue = [&](int ch, int stage) {
        const uint32_t sb0 = smb + stage * STG;
        const int aoff = ch * (32 * D) * 4;
        #pragma unroll
        for (int p = 0; p < PA; p++) {
            if (adst[p] != 0xFFFFFFFFu)
                CP_A16(sb0 + adst[p], asrc[p] + aoff, aszr[p]);
        }
        const int boff = ch * 32 * 256 * 4;
        #pragma unroll
        for (int p = 0; p < 4; p++)
            CP_A16(sb0 + bdst[p], bsrc[p] + boff, 16u);
        CP_COMMIT();
    };

    // ---- fragment row decode (once per tile) ----
    // rows used by this thread: wm*32 + mf*16 + {0,8} + g
    int arow[2][2];
    #pragma unroll
    for (int mf = 0; mf < 2; mf++)
        #pragma unroll
        for (int hh = 0; hh < 2; hh++) {
            const int r  = wm * 32 + mf * 16 + hh * 8 + g;
            const int gr = m0 + r;
            const int z  = gr / D;
            const int i  = gr - z * D;
            arow[mf][hh] = (z - z0) * SD + i;      // element index base
        }
    const int tgD   = tg * D;
    const int bcol  = wn * 64 + g;

    // ---- accumulators ----
    float c[2][8][4];
    #pragma unroll
    for (int mf = 0; mf < 2; mf++)
        #pragma unroll
        for (int nf = 0; nf < 8; nf++)
            #pragma unroll
            for (int q = 0; q < 4; q++) c[mf][nf][q] = 0.0f;

    auto compute = [&](int stage) {
        const float* Af = (const float*)(smem + stage * STG);
        const float* Bf = (const float*)(smem + stage * STG + ABUF);
        #pragma unroll
        for (int s = 0; s < 4; s++) {
            const int ks = 8 * s * D + tgD;
            uint32_t a[2][4];
            #pragma unroll
            for (int mf = 0; mf < 2; mf++) {
                a[mf][0] = f2tf(Af[arow[mf][0] + ks]);
                a[mf][1] = f2tf(Af[arow[mf][1] + ks]);
                a[mf][2] = f2tf(Af[arow[mf][0] + ks + 4 * D]);
                a[mf][3] = f2tf(Af[arow[mf][1] + ks + 4 * D]);
            }
            const int kb = (8 * s + tg) * SB + bcol;
            #pragma unroll
            for (int nf = 0; nf < 8; nf++) {
                const uint32_t b0 = f2tf(Bf[kb + nf * 8]);
                const uint32_t b1 = f2tf(Bf[kb + 4 * SB + nf * 8]);
                mma8(c[0][nf], a[0], b0, b1);
                mma8(c[1][nf], a[1], b0, b1);
            }
        }
    };

    // ---- main pipeline: 3-stage ring, depth-2 prefetch, 1 barrier/chunk ----
    issue(0, 0);
    issue(1, 1);
    #pragma unroll 1
    for (int ch = 0; ch < 8; ch++) {
        if (ch < 7) { CP_WAIT(1); } else { CP_WAIT(0); }
        __syncthreads();
        compute(ch % 3);
        if (ch + 2 < 8) issue(ch + 2, (ch + 2) % 3);
    }

    // ---- epilogue: scatter rows (z,i), scale 1/sqrt(256) ----
    const float S = 0.0625f;
    #pragma unroll
    for (int mf = 0; mf < 2; mf++) {
        #pragma unroll
        for (int rr = 0; rr < 2; rr++) {
            const int gr = m0 + wm * 32 + mf * 16 + rr * 8 + g;
            if (gr < MTOT) {
                const int z = gr / D;
                const int i = gr - z * D;
                float* op = out + (size_t)z * HX_FEAT + XOFF + i
                          + (size_t)(nh * 128) * D;
                #pragma unroll
                for (int nf = 0; nf < 8; nf++) {
                    const int n = wn * 64 + nf * 8 + 2 * tg;
                    if (D == 1) {
                        float2 v;
                        v.x = c[mf][nf][rr * 2 + 0] * S;
                        v.y = c[mf][nf][rr * 2 + 1] * S;
                        *(float2*)(op + n) = v;
                    } else {
                        op[(size_t)n * D]       = c[mf][nf][rr * 2 + 0] * S;
                        op[(size_t)(n + 1) * D] = c[mf][nf][rr * 2 + 1] * S;
                    }
                }
            }
        }
    }
}

// ---------------------------------------------------------------------------
extern "C" void kernel_launch(void* const* d_in, const int* in_sizes, int n_in,
                              void* d_out, int out_size) {
    const float* feat = (const float*)d_in[0];
    const float* wt   = (const float*)d_in[1];
    float* out        = (float*)d_out;

    // per-template smem: 3 stages of (ABUF + BBUF)
    constexpr int SM1 = 3 * (128 * 36 * 4 + 32 * SB * 4);   // 107520
    constexpr int SM3 = 3 * (44 * 104 * 4 + 32 * SB * 4);   // 107136
    constexpr int SM5 = 3 * (27 * 168 * 4 + 32 * SB * 4);   // 106656

    auto k1 = lin_k<1, 0,    0,      50000>;
    auto k3 = lin_k<3, 256,  65536,  150000>;
    auto k5 = lin_k<5, 1024, 131072, 250000>;

    cudaFuncSetAttribute(k1, cudaFuncAttributeMaxDynamicSharedMemorySize, SM1);
    cudaFuncSetAttribute(k3, cudaFuncAttributeMaxDynamicSharedMemorySize, SM3);
    cudaFuncSetAttribute(k5, cudaFuncAttributeMaxDynamicSharedMemorySize, SM5);

    // tiles: d1 391, d3 1172, d5 1954; x2 N-halves (nh = bid&1, adjacent)
    k1<<<391 * 2,  NTH, SM1>>>(feat, wt, out);
    k3<<<1172 * 2, NTH, SM3>>>(feat, wt, out);
    k5<<<1954 * 2, NTH, SM5>>>(feat, wt, out);
}